// round 12
// baseline (speedup 1.0000x reference)
#include <cuda_runtime.h>

// LIF scan: v = v + (x - v)*0.5; s = (v >= 1); v = s ? 0 : v
// x: [B=64, T=200, N=4096] fp32 -> spikes same shape.
//
// FINAL KERNEL (R5 config, best measured: kernel 61.2us, bench 67.6us):
//   - float2 granularity: 131072 threads, ~28 warps/SM, coalesced 8B lanes
//   - depth-1 software pipeline over G=8 timestep groups: next group's 8
//     LDG.64 front-batched (MLP_p1=8) before the current group's serial
//     FFMA/FSEL dependency chain + stores
//   - plain __ldg loads / default stores, block=64, 38 regs
//
// Convergence evidence (R3-R11): six structurally distinct variants all
// plateau at 61.2-61.9us kernel time. Falsified levers: depth-2 pipelining
// (reg cliff), 2x occupancy (neutral), streaming cache hints (regression),
// G=10 bursts (neutral), block=128 (neutral), float4 (equal).
// 420 MB / 61.5us = ~6.8 TB/s = ~85% of 8 TB/s HBM3e spec for a 1:1 R/W
// mix — the DRAM read/write-turnaround ceiling. SM-side metrics all show
// slack (issue 15%, L2 37%); the limiter is the memory system itself.

#define LIF_B 64
#define LIF_T 200
#define LIF_N 4096
#define NV2 (LIF_N / 2)      // 2048 float2 per (b, t) row
#define G 8                  // timesteps per group
#define NGROUP (LIF_T / G)   // 25

__device__ __forceinline__ void lif_step(float& v, float xx, float& s) {
    v = v + (xx - v) * 0.5f;          // exact match to ref op order (x0.5 exact)
    bool fire = (v >= 1.0f);
    s = fire ? 1.0f : 0.0f;
    v = fire ? 0.0f : v;
}

__device__ __forceinline__ void load_group(const float2* __restrict__ xp,
                                           float2 (&xr)[G]) {
    #pragma unroll
    for (int i = 0; i < G; i++) xr[i] = __ldg(xp + i * NV2);
}

__device__ __forceinline__ void process_group(float2& v, const float2 (&xr)[G],
                                              float2* __restrict__ op) {
    #pragma unroll
    for (int i = 0; i < G; i++) {
        float2 s;
        lif_step(v.x, xr[i].x, s.x);
        lif_step(v.y, xr[i].y, s.y);
        op[i * NV2] = s;
    }
}

__global__ __launch_bounds__(64)
void lif_kernel(const float2* __restrict__ x, float2* __restrict__ out) {
    int idx = blockIdx.x * blockDim.x + threadIdx.x;   // 0 .. B*NV2-1
    int b   = idx >> 11;          // / NV2 (NV2 = 2048)
    int n2  = idx & (NV2 - 1);

    size_t base = (size_t)b * LIF_T * NV2 + n2;
    const float2* xp = x + base;
    float2*       op = out + base;

    float2 v = make_float2(0.f, 0.f);
    float2 xa[G], xb[G];

    // prologue: load group 0
    load_group(xp, xa);

    // 24 groups in 12 double-iterations; each half prefetches the next group
    // before touching the serial compute chain of the current one.
    #pragma unroll 1
    for (int gg = 0; gg < (NGROUP - 1) / 2; gg++) {
        load_group(xp + G * NV2, xb);        // prefetch group 2gg+1
        process_group(v, xa, op);            // compute+store group 2gg
        xp += G * NV2; op += G * NV2;

        load_group(xp + G * NV2, xa);        // prefetch group 2gg+2
        process_group(v, xb, op);            // compute+store group 2gg+1
        xp += G * NV2; op += G * NV2;
    }

    // epilogue: group 24 (already loaded into xa)
    process_group(v, xa, op);
}

extern "C" void kernel_launch(void* const* d_in, const int* in_sizes, int n_in,
                              void* d_out, int out_size) {
    const float* x = (const float*)d_in[0];
    // d_in[1] = threshold param, unused by the reference forward
    float* out = (float*)d_out;

    const int total_threads = LIF_B * NV2;   // 131072
    const int block = 64;
    lif_kernel<<<total_threads / block, block>>>(
        (const float2*)x, (float2*)out);
}

// round 13
// speedup vs baseline: 1.0401x; 1.0401x over previous
#include <cuda_runtime.h>

// LIF scan: v = v + (x - v)*0.5; s = (v >= 1); v = s ? 0 : v
// x: [B=64, T=200, N=4096] fp32 -> spikes same shape.
//
// FINAL KERNEL (R5 config; best measured: kernel 61.2us, bench 67.6us).
//   - float2 granularity: 131072 threads, ~28 warps/SM, coalesced 8B lanes
//   - depth-1 software pipeline over G=8 timestep groups: next group's 8
//     LDG.64 front-batched (MLP_p1=8) before the current group's serial
//     FFMA/FSEL dependency chain + stores
//   - plain __ldg loads / default stores, block=64, 38 regs
//
// Convergence evidence (R3-R12): six structurally distinct variants plus
// three repeats of this exact source span 61.2-65.2us kernel time with no
// correlation to source changes — run variance is DVFS/clock noise (R12's
// identical binary showed inflated SM-side %s and deflated DRAM GB/s, the
// signature of a clock-domain shift, not a code effect).
// Falsified levers: depth-2 pipelining (reg cliff), 2x occupancy, streaming
// cache hints, G=10 bursts, block=128, float4. Effective traffic
// 420 MB / ~61.5us = ~6.8 TB/s = ~85% of 8 TB/s HBM3e spec for a 1:1 R/W
// mix — the DRAM read/write-turnaround ceiling. Traffic is irreducible
// (each byte touched exactly once, fp32 fixed by harness); the kernel is
// closed at the memory-system ceiling.

#define LIF_B 64
#define LIF_T 200
#define LIF_N 4096
#define NV2 (LIF_N / 2)      // 2048 float2 per (b, t) row
#define G 8                  // timesteps per group
#define NGROUP (LIF_T / G)   // 25

__device__ __forceinline__ void lif_step(float& v, float xx, float& s) {
    v = v + (xx - v) * 0.5f;          // exact match to ref op order (x0.5 exact)
    bool fire = (v >= 1.0f);
    s = fire ? 1.0f : 0.0f;
    v = fire ? 0.0f : v;
}

__device__ __forceinline__ void load_group(const float2* __restrict__ xp,
                                           float2 (&xr)[G]) {
    #pragma unroll
    for (int i = 0; i < G; i++) xr[i] = __ldg(xp + i * NV2);
}

__device__ __forceinline__ void process_group(float2& v, const float2 (&xr)[G],
                                              float2* __restrict__ op) {
    #pragma unroll
    for (int i = 0; i < G; i++) {
        float2 s;
        lif_step(v.x, xr[i].x, s.x);
        lif_step(v.y, xr[i].y, s.y);
        op[i * NV2] = s;
    }
}

__global__ __launch_bounds__(64)
void lif_kernel(const float2* __restrict__ x, float2* __restrict__ out) {
    int idx = blockIdx.x * blockDim.x + threadIdx.x;   // 0 .. B*NV2-1
    int b   = idx >> 11;          // / NV2 (NV2 = 2048)
    int n2  = idx & (NV2 - 1);

    size_t base = (size_t)b * LIF_T * NV2 + n2;
    const float2* xp = x + base;
    float2*       op = out + base;

    float2 v = make_float2(0.f, 0.f);
    float2 xa[G], xb[G];

    // prologue: load group 0
    load_group(xp, xa);

    // 24 groups in 12 double-iterations; each half prefetches the next group
    // before touching the serial compute chain of the current one.
    #pragma unroll 1
    for (int gg = 0; gg < (NGROUP - 1) / 2; gg++) {
        load_group(xp + G * NV2, xb);        // prefetch group 2gg+1
        process_group(v, xa, op);            // compute+store group 2gg
        xp += G * NV2; op += G * NV2;

        load_group(xp + G * NV2, xa);        // prefetch group 2gg+2
        process_group(v, xb, op);            // compute+store group 2gg+1
        xp += G * NV2; op += G * NV2;
    }

    // epilogue: group 24 (already loaded into xa)
    process_group(v, xa, op);
}

extern "C" void kernel_launch(void* const* d_in, const int* in_sizes, int n_in,
                              void* d_out, int out_size) {
    const float* x = (const float*)d_in[0];
    // d_in[1] = threshold param, unused by the reference forward
    float* out = (float*)d_out;

    const int total_threads = LIF_B * NV2;   // 131072
    const int block = 64;
    lif_kernel<<<total_threads / block, block>>>(
        (const float2*)x, (float2*)out);
}

// round 15
// speedup vs baseline: 1.0475x; 1.0070x over previous
#include <cuda_runtime.h>

// LIF scan: v = v + (x - v)*0.5; s = (v >= 1); v = s ? 0 : v
// x: [B=64, T=200, N=4096] fp32 -> spikes same shape.
//
// FINAL KERNEL (R5 config; best measured: kernel 61.2us, bench 67.6us).
//   - float2 granularity: 131072 threads, ~28 warps/SM, coalesced 8B lanes
//   - depth-1 software pipeline over G=8 timestep groups: next group's 8
//     LDG.64 front-batched (MLP_p1=8) before the current group's serial
//     FFMA/FSEL dependency chain + stores
//   - plain __ldg loads / default stores, block=64, 38 regs
//
// Convergence evidence (R3-R13): six structurally distinct variants plus
// four repeats of this exact source. Fixed-binary spread: kernel
// 61.2/61.9/65.2/63.0us, bench 67.6/68.1/71.3/68.6us — run variance (DVFS)
// fully brackets every source-level delta observed. Falsified levers:
// depth-2 pipelining (reg cliff), 2x occupancy, streaming cache hints,
// G=10 bursts, block=128, float4. Effective traffic 420 MB / 61.5us =
// ~6.8 TB/s = ~85% of 8 TB/s HBM3e spec for a 1:1 R/W mix — the DRAM
// read/write-turnaround ceiling. Traffic is irreducible (each byte touched
// exactly once, fp32 fixed by harness). Closed at the memory-system
// ceiling; further rounds should resubmit this kernel unchanged.

#define LIF_B 64
#define LIF_T 200
#define LIF_N 4096
#define NV2 (LIF_N / 2)      // 2048 float2 per (b, t) row
#define G 8                  // timesteps per group
#define NGROUP (LIF_T / G)   // 25

__device__ __forceinline__ void lif_step(float& v, float xx, float& s) {
    v = v + (xx - v) * 0.5f;          // exact match to ref op order (x0.5 exact)
    bool fire = (v >= 1.0f);
    s = fire ? 1.0f : 0.0f;
    v = fire ? 0.0f : v;
}

__device__ __forceinline__ void load_group(const float2* __restrict__ xp,
                                           float2 (&xr)[G]) {
    #pragma unroll
    for (int i = 0; i < G; i++) xr[i] = __ldg(xp + i * NV2);
}

__device__ __forceinline__ void process_group(float2& v, const float2 (&xr)[G],
                                              float2* __restrict__ op) {
    #pragma unroll
    for (int i = 0; i < G; i++) {
        float2 s;
        lif_step(v.x, xr[i].x, s.x);
        lif_step(v.y, xr[i].y, s.y);
        op[i * NV2] = s;
    }
}

__global__ __launch_bounds__(64)
void lif_kernel(const float2* __restrict__ x, float2* __restrict__ out) {
    int idx = blockIdx.x * blockDim.x + threadIdx.x;   // 0 .. B*NV2-1
    int b   = idx >> 11;          // / NV2 (NV2 = 2048)
    int n2  = idx & (NV2 - 1);

    size_t base = (size_t)b * LIF_T * NV2 + n2;
    const float2* xp = x + base;
    float2*       op = out + base;

    float2 v = make_float2(0.f, 0.f);
    float2 xa[G], xb[G];

    // prologue: load group 0
    load_group(xp, xa);

    // 24 groups in 12 double-iterations; each half prefetches the next group
    // before touching the serial compute chain of the current one.
    #pragma unroll 1
    for (int gg = 0; gg < (NGROUP - 1) / 2; gg++) {
        load_group(xp + G * NV2, xb);        // prefetch group 2gg+1
        process_group(v, xa, op);            // compute+store group 2gg
        xp += G * NV2; op += G * NV2;

        load_group(xp + G * NV2, xa);        // prefetch group 2gg+2
        process_group(v, xb, op);            // compute+store group 2gg+1
        xp += G * NV2; op += G * NV2;
    }

    // epilogue: group 24 (already loaded into xa)
    process_group(v, xa, op);
}

extern "C" void kernel_launch(void* const* d_in, const int* in_sizes, int n_in,
                              void* d_out, int out_size) {
    const float* x = (const float*)d_in[0];
    // d_in[1] = threshold param, unused by the reference forward
    float* out = (float*)d_out;

    const int total_threads = LIF_B * NV2;   // 131072
    const int block = 64;
    lif_kernel<<<total_threads / block, block>>>(
        (const float2*)x, (float2*)out);
}